// round 12
// baseline (speedup 1.0000x reference)
#include <cuda_runtime.h>
#include <cstdint>

// out[o*256+k][h][m] = sum_{i,j} w[i][k][j] * xp[m+j], xp = padded/rolled row.
// Grid 112 = (o:2, kq:4, h:14). Block 512 = 16 warps; warp g owns i in [16g,16g+16).
// Lane = adjacent channel pair k0 = kq*64 + 2*lane (f32x2 lanes = 2 output chans).
// Weights: verbatim cp.async (coalesced float4), 2 halves. Mainloop per il:
// 3 LDS.64 (w) + 3 mov.b64 + 8 bcast LDS.128 (x) + TWO fused asm blocks of
// 21 fma.rn.f32x2 with "+l" accumulators (no per-statement operand re-binding
// -> no pair-alignment MOVs). Deterministic smem reduction.

#define W_FLOATS (256 * 192)              // 192KB raw weights
#define X_U64    (16 * 16 * 16)           // 32KB duplicated-pair x table
#define SMEM_BYTES (W_FLOATS * 4 + X_U64 * 8)   // 224KB

extern __shared__ float smem[];

__device__ __forceinline__ uint64_t pkab(float a, float b) {
    uint64_t r;
    asm("mov.b64 %0, {%1, %2};" : "=l"(r)
        : "r"(__float_as_uint(a)), "r"(__float_as_uint(b)));
    return r;
}
__device__ __forceinline__ void cp16(uint32_t s, const void* g) {
    asm volatile("cp.async.cg.shared.global [%0], [%1], 16;" :: "r"(s), "l"(g) : "memory");
}
__device__ __forceinline__ void cp_commit() {
    asm volatile("cp.async.commit_group;" ::: "memory");
}
template <int N> __device__ __forceinline__ void cp_wait() {
    asm volatile("cp.async.wait_group %0;" :: "n"(N) : "memory");
}

// 21 packed FMAs: a[t] += W0*X[t] + W1*X[t+1] + W2*X[t+2], t = 0..6
#define FMA7(a0,a1,a2,a3,a4,a5,a6, W0,W1,W2, X0,X1,X2,X3,X4,X5,X6,X7,X8)     \
    asm("fma.rn.f32x2 %0, %7, %10, %0;\n\t"                                  \
        "fma.rn.f32x2 %1, %7, %11, %1;\n\t"                                  \
        "fma.rn.f32x2 %2, %7, %12, %2;\n\t"                                  \
        "fma.rn.f32x2 %3, %7, %13, %3;\n\t"                                  \
        "fma.rn.f32x2 %4, %7, %14, %4;\n\t"                                  \
        "fma.rn.f32x2 %5, %7, %15, %5;\n\t"                                  \
        "fma.rn.f32x2 %6, %7, %16, %6;\n\t"                                  \
        "fma.rn.f32x2 %0, %8, %11, %0;\n\t"                                  \
        "fma.rn.f32x2 %1, %8, %12, %1;\n\t"                                  \
        "fma.rn.f32x2 %2, %8, %13, %2;\n\t"                                  \
        "fma.rn.f32x2 %3, %8, %14, %3;\n\t"                                  \
        "fma.rn.f32x2 %4, %8, %15, %4;\n\t"                                  \
        "fma.rn.f32x2 %5, %8, %16, %5;\n\t"                                  \
        "fma.rn.f32x2 %6, %8, %17, %6;\n\t"                                  \
        "fma.rn.f32x2 %0, %9, %12, %0;\n\t"                                  \
        "fma.rn.f32x2 %1, %9, %13, %1;\n\t"                                  \
        "fma.rn.f32x2 %2, %9, %14, %2;\n\t"                                  \
        "fma.rn.f32x2 %3, %9, %15, %3;\n\t"                                  \
        "fma.rn.f32x2 %4, %9, %16, %4;\n\t"                                  \
        "fma.rn.f32x2 %5, %9, %17, %5;\n\t"                                  \
        "fma.rn.f32x2 %6, %9, %18, %6;"                                      \
        : "+l"(a0), "+l"(a1), "+l"(a2), "+l"(a3), "+l"(a4), "+l"(a5), "+l"(a6) \
        : "l"(W0), "l"(W1), "l"(W2),                                          \
          "l"(X0), "l"(X1), "l"(X2), "l"(X3), "l"(X4), "l"(X5), "l"(X6),      \
          "l"(X7), "l"(X8))

__global__ __launch_bounds__(512, 1)
void fused_conv_kernel(const float* __restrict__ x,
                       const float* __restrict__ w,
                       float* __restrict__ out) {
    const int bx = blockIdx.x;           // 0..111
    const int o  = bx / 56;
    const int kq = (bx / 14) & 3;
    const int h  = bx % 14;
    const int tid  = threadIdx.x;
    const int g    = tid >> 5;           // warp / i-group 0..15
    const int lane = tid & 31;
    const int n    = (h + 13) % 14;      // undo roll along H

    float*    swr = smem;                            // SR[i][192]
    uint64_t* sxd = (uint64_t*)(smem + W_FLOATS);    // SX[g][il][a]

    const uint32_t s_u32 = (uint32_t)__cvta_generic_to_shared(smem);
    const float* wb = w + (size_t)kq * 192;

    // ---- cp.async weight copy, 2 halves split by (i mod 16) ----
#define ISSUE_HALF(cc)                                                        \
    {                                                                         \
        _Pragma("unroll")                                                     \
        for (int it = 0; it < 12; it++) {                                     \
            const int f4  = it * 512 + tid;                                   \
            const int r   = f4 / 48;                                          \
            const int col = f4 % 48;                                          \
            const int i   = (r >> 3) * 16 + (cc) * 8 + (r & 7);               \
            cp16(s_u32 + (uint32_t)(i * 192 + col * 4) * 4,                   \
                 wb + (size_t)i * 768 + col * 4);                             \
        }                                                                     \
        cp_commit();                                                          \
    }
    ISSUE_HALF(0)
    ISSUE_HALF(1)

    // ---- stage x (duplicated pairs), per-warp private ----
    {
        const float* xb = x + ((size_t)o * 256 + g * 16) * 196 + n * 14;
#pragma unroll
        for (int r = 0; r < 8; r++) {
            const int idx = r * 32 + lane;       // 0..255
            const int il = idx >> 4;
            const int a  = idx & 15;
            float v = 0.f;
            if (a >= 1 && a <= 14) v = xb[(size_t)il * 196 + (a + 12) % 14];
            sxd[g * 256 + idx] = pkab(v, v);
        }
    }

    uint64_t acc[14];
#pragma unroll
    for (int m = 0; m < 14; m++) acc[m] = 0ull;

    // ---- mainloop: 2 halves x 8 il ----
#pragma unroll
    for (int half = 0; half < 2; half++) {
        if (half == 0) cp_wait<1>(); else cp_wait<0>();
        __syncthreads();

#pragma unroll
        for (int q = 0; q < 8; q++) {
            const int il = half * 8 + q;
            const int i  = g * 16 + il;
            // raw 6 floats: [a0 a1 | a2 b0 | b1 b2] for channels (k0, k0+1)
            const float2* wr = (const float2*)(swr + (size_t)i * 192 + lane * 6);
            const float2 A = wr[0];
            const float2 B = wr[1];
            const float2 C = wr[2];
            const uint64_t W0 = pkab(A.x, B.y);
            const uint64_t W1 = pkab(A.y, C.x);
            const uint64_t W2 = pkab(B.x, C.y);

            const ulonglong2* xd = (const ulonglong2*)(sxd + g * 256 + il * 16);
            const ulonglong2 x0 = xd[0];
            const ulonglong2 x1 = xd[1];
            const ulonglong2 x2 = xd[2];
            const ulonglong2 x3 = xd[3];
            const ulonglong2 x4 = xd[4];
            const ulonglong2 x5 = xd[5];
            const ulonglong2 x6 = xd[6];
            const ulonglong2 x7 = xd[7];

            FMA7(acc[0], acc[1], acc[2], acc[3], acc[4], acc[5], acc[6],
                 W0, W1, W2,
                 x0.x, x0.y, x1.x, x1.y, x2.x, x2.y, x3.x, x3.y, x4.x);
            FMA7(acc[7], acc[8], acc[9], acc[10], acc[11], acc[12], acc[13],
                 W0, W1, W2,
                 x3.y, x4.x, x4.y, x5.x, x5.y, x6.x, x6.y, x7.x, x7.y);
        }
    }

    // ---- cross-warp reduction (reuse weight region) ----
    __syncthreads();
    uint64_t* ps = (uint64_t*)smem;      // ps[(g*32+lane)*14 + m]
#pragma unroll
    for (int m = 0; m < 14; m++)
        ps[((size_t)(g * 32 + lane)) * 14 + m] = acc[m];
    __syncthreads();

    if (tid < 448) {
        const int lk = tid / 14;         // lane-pair 0..31
        const int m  = tid % 14;
        float lo = 0.f, hi = 0.f;
#pragma unroll
        for (int gg = 0; gg < 16; gg++) {    // fixed order -> deterministic
            const float2 v = ((const float2*)ps)[(gg * 32 + lk) * 14 + m];
            lo += v.x;
            hi += v.y;
        }
        const int cg = o * 256 + kq * 64 + 2 * lk;
        out[(size_t)cg * 196 + h * 14 + m]       = lo;
        out[(size_t)(cg + 1) * 196 + h * 14 + m] = hi;
    }
}

extern "C" void kernel_launch(void* const* d_in, const int* in_sizes, int n_in,
                              void* d_out, int out_size) {
    const float* x = (const float*)d_in[0];   // (1,512,14,14)
    const float* w = (const float*)d_in[1];   // (256,256,3)
    float* out = (float*)d_out;

    cudaFuncSetAttribute(fused_conv_kernel,
                         cudaFuncAttributeMaxDynamicSharedMemorySize, SMEM_BYTES);
    fused_conv_kernel<<<112, 512, SMEM_BYTES>>>(x, w, out);
}

// round 13
// speedup vs baseline: 1.0021x; 1.0021x over previous
#include <cuda_runtime.h>
#include <cstdint>

// out[o*256+k][h][m] = sum_{i,j} w[i][k][j] * xp[m+j], xp = padded/rolled row.
// Grid 112 = (o:2, kq:4, h:14). Block 1024 = 32 warps; warp g owns i in [8g, 8g+8).
// Lane = adjacent channel pair k0 = kq*64 + 2*lane (f32x2 lanes = 2 output chans).
// Weights: verbatim cp.async (coalesced float4), 2 halves split by (i mod 8).
// Mainloop per il: 3 LDS.64 (w) + 3 mov.b64 + 8 bcast LDS.128 (x) + 42 FFMA2.
// 8 warps/SMSP for latency coverage. Deterministic 32-way smem reduction.

#define W_FLOATS (256 * 192)              // 192KB raw weights
#define X_U64    (256 * 16)               // 32KB duplicated-pair x table
#define SMEM_BYTES (W_FLOATS * 4 + X_U64 * 8)   // 224KB

extern __shared__ float smem[];

__device__ __forceinline__ uint64_t pkab(float a, float b) {
    uint64_t r;
    asm("mov.b64 %0, {%1, %2};" : "=l"(r)
        : "r"(__float_as_uint(a)), "r"(__float_as_uint(b)));
    return r;
}
__device__ __forceinline__ void cp16(uint32_t s, const void* g) {
    asm volatile("cp.async.cg.shared.global [%0], [%1], 16;" :: "r"(s), "l"(g) : "memory");
}
__device__ __forceinline__ void cp_commit() {
    asm volatile("cp.async.commit_group;" ::: "memory");
}
template <int N> __device__ __forceinline__ void cp_wait() {
    asm volatile("cp.async.wait_group %0;" :: "n"(N) : "memory");
}

// 21 packed FMAs: a[t] += W0*X[t] + W1*X[t+1] + W2*X[t+2], t = 0..6
#define FMA7(a0,a1,a2,a3,a4,a5,a6, W0,W1,W2, X0,X1,X2,X3,X4,X5,X6,X7,X8)     \
    asm("fma.rn.f32x2 %0, %7, %10, %0;\n\t"                                  \
        "fma.rn.f32x2 %1, %7, %11, %1;\n\t"                                  \
        "fma.rn.f32x2 %2, %7, %12, %2;\n\t"                                  \
        "fma.rn.f32x2 %3, %7, %13, %3;\n\t"                                  \
        "fma.rn.f32x2 %4, %7, %14, %4;\n\t"                                  \
        "fma.rn.f32x2 %5, %7, %15, %5;\n\t"                                  \
        "fma.rn.f32x2 %6, %7, %16, %6;\n\t"                                  \
        "fma.rn.f32x2 %0, %8, %11, %0;\n\t"                                  \
        "fma.rn.f32x2 %1, %8, %12, %1;\n\t"                                  \
        "fma.rn.f32x2 %2, %8, %13, %2;\n\t"                                  \
        "fma.rn.f32x2 %3, %8, %14, %3;\n\t"                                  \
        "fma.rn.f32x2 %4, %8, %15, %4;\n\t"                                  \
        "fma.rn.f32x2 %5, %8, %16, %5;\n\t"                                  \
        "fma.rn.f32x2 %6, %8, %17, %6;\n\t"                                  \
        "fma.rn.f32x2 %0, %9, %12, %0;\n\t"                                  \
        "fma.rn.f32x2 %1, %9, %13, %1;\n\t"                                  \
        "fma.rn.f32x2 %2, %9, %14, %2;\n\t"                                  \
        "fma.rn.f32x2 %3, %9, %15, %3;\n\t"                                  \
        "fma.rn.f32x2 %4, %9, %16, %4;\n\t"                                  \
        "fma.rn.f32x2 %5, %9, %17, %5;\n\t"                                  \
        "fma.rn.f32x2 %6, %9, %18, %6;"                                      \
        : "+l"(a0), "+l"(a1), "+l"(a2), "+l"(a3), "+l"(a4), "+l"(a5), "+l"(a6) \
        : "l"(W0), "l"(W1), "l"(W2),                                          \
          "l"(X0), "l"(X1), "l"(X2), "l"(X3), "l"(X4), "l"(X5), "l"(X6),      \
          "l"(X7), "l"(X8))

__global__ __launch_bounds__(1024, 1)
void fused_conv_kernel(const float* __restrict__ x,
                       const float* __restrict__ w,
                       float* __restrict__ out) {
    const int bx = blockIdx.x;           // 0..111
    const int o  = bx / 56;
    const int kq = (bx / 14) & 3;
    const int h  = bx % 14;
    const int tid  = threadIdx.x;
    const int g    = tid >> 5;           // warp / i-group 0..31 (8 i each)
    const int lane = tid & 31;
    const int n    = (h + 13) % 14;      // undo roll along H

    float*    swr = smem;                            // SR[i][192]
    uint64_t* sxd = (uint64_t*)(smem + W_FLOATS);    // SX[i][a] global table

    const uint32_t s_u32 = (uint32_t)__cvta_generic_to_shared(smem);
    const float* wb = w + (size_t)kq * 192;

    // ---- cp.async weight copy, 2 halves split by (i mod 8) ----
    // half c, row r (0..127): i = (r>>2)*8 + c*4 + (r&3); 48 f4 per row.
#define ISSUE_HALF(cc)                                                        \
    {                                                                         \
        _Pragma("unroll")                                                     \
        for (int it = 0; it < 6; it++) {                                      \
            const int f4  = it * 1024 + tid;        /* 0..6143 */             \
            const int r   = f4 / 48;                                          \
            const int col = f4 % 48;                                          \
            const int i   = (r >> 2) * 8 + (cc) * 4 + (r & 3);                \
            cp16(s_u32 + (uint32_t)(i * 192 + col * 4) * 4,                   \
                 wb + (size_t)i * 768 + col * 4);                             \
        }                                                                     \
        cp_commit();                                                          \
    }
    ISSUE_HALF(0)
    ISSUE_HALF(1)

    // ---- stage x (duplicated pairs), global table SX[i][a] ----
    // xp[a] = (a in [1,14]) ? x[(o*256+i)*196 + n*14 + (a+12)%14] : 0
    {
        const float* xb = x + ((size_t)o * 256) * 196 + n * 14;
#pragma unroll
        for (int r = 0; r < 4; r++) {
            const int idx = r * 1024 + tid;      // 0..4095
            const int i = idx >> 4;
            const int a = idx & 15;
            float v = 0.f;
            if (a >= 1 && a <= 14) v = xb[(size_t)i * 196 + (a + 12) % 14];
            sxd[idx] = pkab(v, v);
        }
    }

    uint64_t acc[14];
#pragma unroll
    for (int m = 0; m < 14; m++) acc[m] = 0ull;

    // ---- mainloop: 2 halves x 4 il ----
#pragma unroll
    for (int half = 0; half < 2; half++) {
        if (half == 0) cp_wait<1>(); else cp_wait<0>();
        __syncthreads();                 // half's weights (+x table on half 0) visible

#pragma unroll
        for (int q = 0; q < 4; q++) {
            const int il = half * 4 + q;
            const int i  = g * 8 + il;
            // raw 6 floats: [a0 a1 | a2 b0 | b1 b2] for channels (k0, k0+1)
            const float2* wr = (const float2*)(swr + (size_t)i * 192 + lane * 6);
            const float2 A = wr[0];
            const float2 B = wr[1];
            const float2 C = wr[2];
            const uint64_t W0 = pkab(A.x, B.y);
            const uint64_t W1 = pkab(A.y, C.x);
            const uint64_t W2 = pkab(B.x, C.y);

            const ulonglong2* xd = (const ulonglong2*)(sxd + (size_t)i * 16);
            const ulonglong2 x0 = xd[0];
            const ulonglong2 x1 = xd[1];
            const ulonglong2 x2 = xd[2];
            const ulonglong2 x3 = xd[3];
            const ulonglong2 x4 = xd[4];
            const ulonglong2 x5 = xd[5];
            const ulonglong2 x6 = xd[6];
            const ulonglong2 x7 = xd[7];

            FMA7(acc[0], acc[1], acc[2], acc[3], acc[4], acc[5], acc[6],
                 W0, W1, W2,
                 x0.x, x0.y, x1.x, x1.y, x2.x, x2.y, x3.x, x3.y, x4.x);
            FMA7(acc[7], acc[8], acc[9], acc[10], acc[11], acc[12], acc[13],
                 W0, W1, W2,
                 x3.y, x4.x, x4.y, x5.x, x5.y, x6.x, x6.y, x7.x, x7.y);
        }
    }

    // ---- cross-warp reduction (reuse weight region) ----
    __syncthreads();
    uint64_t* ps = (uint64_t*)smem;      // ps[(g*32+lane)*14 + m] : 114KB
#pragma unroll
    for (int m = 0; m < 14; m++)
        ps[((size_t)(g * 32 + lane)) * 14 + m] = acc[m];
    __syncthreads();

    if (tid < 448) {
        const int lk = tid / 14;         // lane-pair 0..31
        const int m  = tid % 14;
        float lo = 0.f, hi = 0.f;
#pragma unroll
        for (int gg = 0; gg < 32; gg++) {    // fixed order -> deterministic
            const float2 v = ((const float2*)ps)[(gg * 32 + lk) * 14 + m];
            lo += v.x;
            hi += v.y;
        }
        const int cg = o * 256 + kq * 64 + 2 * lk;
        out[(size_t)cg * 196 + h * 14 + m]       = lo;
        out[(size_t)(cg + 1) * 196 + h * 14 + m] = hi;
    }
}

extern "C" void kernel_launch(void* const* d_in, const int* in_sizes, int n_in,
                              void* d_out, int out_size) {
    const float* x = (const float*)d_in[0];   // (1,512,14,14)
    const float* w = (const float*)d_in[1];   // (256,256,3)
    float* out = (float*)d_out;

    cudaFuncSetAttribute(fused_conv_kernel,
                         cudaFuncAttributeMaxDynamicSharedMemorySize, SMEM_BYTES);
    fused_conv_kernel<<<112, 1024, SMEM_BYTES>>>(x, w, out);
}

// round 15
// speedup vs baseline: 1.1597x; 1.1572x over previous
#include <cuda_runtime.h>
#include <cstdint>

// R8 design at 1024 threads (R14 with the chunk-copy overrun fixed).
// out[o*256+k][h][m] = sum_{i,j} w[i][k][j] * xp[m+j], xp = padded/rolled row.
// Grid 112 = (o:2, kq:4, h:14). Block 1024 = 16 i-groups x 64 k.
// Thread: one k, all 14 m as 7 f32x2 accumulators, 16 i's (8 chunks x 2 il).
// Weights cp.async 3-deep pipelined (one barrier per chunk). Cross-group
// reduction in smem, fixed order (deterministic).

#define CHUNKS 8
#define NBUF   3
#define CHUNK_FLOATS (32 * 192)          // 32 rows x (64 k x 3 taps) = 24KB
#define CHUNK_F4     (CHUNK_FLOATS / 4)  // 1536 float4 per chunk
#define SXE_OFF (NBUF * CHUNK_FLOATS)    // 256 x 16 floats
#define SXO_OFF (SXE_OFF + 4096)
#define SMEM_FLOATS (SXO_OFF + 4096)     // 26624 floats = 104KB
#define SMEM_BYTES (SMEM_FLOATS * 4)

extern __shared__ float smem[];

__device__ __forceinline__ uint64_t pk2(float v) {
    uint64_t r;
    asm("mov.b64 %0, {%1, %1};" : "=l"(r) : "r"(__float_as_uint(v)));
    return r;
}
__device__ __forceinline__ uint64_t ffma2(uint64_t a, uint64_t b, uint64_t c) {
    uint64_t d;
    asm("fma.rn.f32x2 %0, %1, %2, %3;" : "=l"(d) : "l"(a), "l"(b), "l"(c));
    return d;
}
__device__ __forceinline__ void cp16(uint32_t s, const void* g) {
    asm volatile("cp.async.cg.shared.global [%0], [%1], 16;" :: "r"(s), "l"(g) : "memory");
}
__device__ __forceinline__ void cp_commit() {
    asm volatile("cp.async.commit_group;" ::: "memory");
}
template <int N> __device__ __forceinline__ void cp_wait() {
    asm volatile("cp.async.wait_group %0;" :: "n"(N) : "memory");
}

__global__ __launch_bounds__(1024, 1)
void fused_conv_kernel(const float* __restrict__ x,
                       const float* __restrict__ w,
                       float* __restrict__ out) {
    const int bx = blockIdx.x;          // 0..111
    const int o  = bx / 56;
    const int kq = (bx / 14) & 3;       // 64-k quarter
    const int h  = bx % 14;
    const int tid = threadIdx.x;
    const int g   = tid >> 6;           // i-group 0..15 (16 i each)
    const int tx  = tid & 63;           // k within quarter
    const int n   = (h + 13) % 14;      // undo roll along H

    const uint32_t s_u32 = (uint32_t)__cvta_generic_to_shared(smem);

    // ---- weight chunk copy: chunk c, buffer row r (0..31): i = (r>>1)*16 + c*2 + (r&1)
    // row = 192 contiguous floats: w[i][kq*64 .. +64][3] = w + i*768 + kq*192.
    // 1536 float4 per chunk; 1024 threads -> pass 0 full, pass 1 tids < 512.
    const float* wb = w + (size_t)kq * 192;
#define ISSUE_CHUNK(cc, buf)                                                     \
    {                                                                            \
        _Pragma("unroll")                                                        \
        for (int it = 0; it < 2; it++) {                                         \
            const int f4 = it * 1024 + tid;                                      \
            if (f4 < CHUNK_F4) {                                                 \
                const int r = f4 / 48;                                           \
                const int within = f4 % 48;                                      \
                const int i = (r >> 1) * 16 + (cc) * 2 + (r & 1);                \
                cp16(s_u32 + (uint32_t)((buf) * CHUNK_FLOATS + r * 192 + within * 4) * 4, \
                     wb + (size_t)i * 768 + within * 4);                         \
            }                                                                    \
        }                                                                        \
        cp_commit();                                                             \
    }

    ISSUE_CHUNK(0, 0)
    ISSUE_CHUNK(1, 1)

    // ---- stage x: sxe[i][mm] = xp[mm], sxo[i][mm] = xp[mm+1]
    // xp[a] = (a in [1,14]) ? x[o*256+i][n][(a+12)%14] : 0
    {
        const float* xbase = x + ((size_t)o * 256) * 196 + n * 14;
#pragma unroll
        for (int rep = 0; rep < 4; rep++) {
            const int idx = rep * 1024 + tid;      // 0..4095
            const int i = idx >> 4;
            const int mm = idx & 15;
            float ve = 0.f, vo = 0.f;
            if (mm >= 1 && mm <= 14) ve = xbase[(size_t)i * 196 + (mm + 12) % 14];
            if (mm + 1 <= 14)        vo = xbase[(size_t)i * 196 + (mm + 13) % 14];
            smem[SXE_OFF + idx] = ve;
            smem[SXO_OFF + idx] = vo;
        }
    }

    uint64_t A[7];
#pragma unroll
    for (int p = 0; p < 7; p++) A[p] = 0ull;

    // ---- main loop: 8 chunks, 3-deep pipeline, one barrier per chunk ----
#pragma unroll
    for (int c = 0; c < CHUNKS; c++) {
        if (c < CHUNKS - 1) cp_wait<1>(); else cp_wait<0>();   // chunk c landed
        __syncthreads();   // all warps past chunk c-1 (and x staging on c=0)
        if (c + 2 < CHUNKS) ISSUE_CHUNK(c + 2, (c + 2) % NBUF)

        const float* swp = smem + (c % NBUF) * CHUNK_FLOATS + (g * 2) * 192 + tx * 3;
        const float* xe  = smem + SXE_OFF + (size_t)(g * 16 + c * 2) * 16;
        const float* xo  = smem + SXO_OFF + (size_t)(g * 16 + c * 2) * 16;

#pragma unroll
        for (int il = 0; il < 2; il++) {
            const uint64_t W0 = pk2(swp[il * 192 + 0]);
            const uint64_t W1 = pk2(swp[il * 192 + 1]);
            const uint64_t W2 = pk2(swp[il * 192 + 2]);

            const ulonglong2 e01 = *(const ulonglong2*)(xe + il * 16);
            const ulonglong2 e23 = *(const ulonglong2*)(xe + il * 16 + 4);
            const ulonglong2 e45 = *(const ulonglong2*)(xe + il * 16 + 8);
            const ulonglong2 e67 = *(const ulonglong2*)(xe + il * 16 + 12);
            const ulonglong2 o01 = *(const ulonglong2*)(xo + il * 16);
            const ulonglong2 o23 = *(const ulonglong2*)(xo + il * 16 + 4);
            const ulonglong2 o45 = *(const ulonglong2*)(xo + il * 16 + 8);
            const uint64_t   o6  = *(const uint64_t*)  (xo + il * 16 + 12);

            uint64_t E[8] = {e01.x, e01.y, e23.x, e23.y, e45.x, e45.y, e67.x, e67.y};
            uint64_t O[7] = {o01.x, o01.y, o23.x, o23.y, o45.x, o45.y, o6};

#pragma unroll
            for (int p = 0; p < 7; p++) {
                A[p] = ffma2(W0, E[p],     A[p]);
                A[p] = ffma2(W1, O[p],     A[p]);
                A[p] = ffma2(W2, E[p + 1], A[p]);
            }
        }
    }

    // ---- cross-group reduction in smem ----
    __syncthreads();                     // all warps done with chunk-7 buffer
    uint64_t* ps = (uint64_t*)smem;      // ps[g*448 + tx*7 + p], 16*448 u64 = 56KB
#pragma unroll
    for (int p = 0; p < 7; p++)
        ps[(size_t)g * 448 + tx * 7 + p] = A[p];
    __syncthreads();

    if (tid < 448) {
        const int k = tid / 7;           // 0..63
        const int p = tid % 7;
        float vlo = 0.f, vhi = 0.f;
#pragma unroll
        for (int gg = 0; gg < 16; gg++) { // fixed order -> deterministic
            const float2 v = ((const float2*)ps)[gg * 448 + k * 7 + p];
            vlo += v.x;
            vhi += v.y;
        }
        const int cg = o * 256 + kq * 64 + k;
        float2 s; s.x = vlo; s.y = vhi;
        *(float2*)&out[(size_t)cg * 196 + h * 14 + 2 * p] = s;
    }
}

extern "C" void kernel_launch(void* const* d_in, const int* in_sizes, int n_in,
                              void* d_out, int out_size) {
    const float* x = (const float*)d_in[0];   // (1,512,14,14)
    const float* w = (const float*)d_in[1];   // (256,256,3)
    float* out = (float*)d_out;

    cudaFuncSetAttribute(fused_conv_kernel,
                         cudaFuncAttributeMaxDynamicSharedMemorySize, SMEM_BYTES);
    fused_conv_kernel<<<112, 1024, SMEM_BYTES>>>(x, w, out);
}

// round 16
// speedup vs baseline: 1.1830x; 1.0201x over previous
#include <cuda_runtime.h>
#include <cstdint>

// Monolithic-staging variant of the R8/R15 clean-mix design.
// out[o*256+k][h][m] = sum_{i,j} w[i][k][j] * xp[m+j], xp = padded/rolled row.
// Grid 112 = (o:2, kq:4, h:14). Block 1024 = 16 i-groups x 64 k; thread = one k,
// 7 f32x2 accumulators (all 14 m), 16 i's. ALL weights (192KB) staged via
// cp.async in 2 halves split by il<8 / il>=8 -> mainloop is two straight-line
// 8-il runs, 2 barriers total. Deterministic smem reduction.

#define W_FLOATS (256 * 192)             // SR[i][192] : 192KB
#define SXE_OFF  W_FLOATS                // sxe: 256 x 16 floats (16KB)
#define SXO_OFF  (SXE_OFF + 4096)        // sxo: 16KB
#define SMEM_FLOATS (SXO_OFF + 4096)     // 57344 floats = 224KB
#define SMEM_BYTES  (SMEM_FLOATS * 4)

extern __shared__ float smem[];

__device__ __forceinline__ uint64_t pk2(float v) {
    uint64_t r;
    asm("mov.b64 %0, {%1, %1};" : "=l"(r) : "r"(__float_as_uint(v)));
    return r;
}
__device__ __forceinline__ uint64_t ffma2(uint64_t a, uint64_t b, uint64_t c) {
    uint64_t d;
    asm("fma.rn.f32x2 %0, %1, %2, %3;" : "=l"(d) : "l"(a), "l"(b), "l"(c));
    return d;
}
__device__ __forceinline__ void cp16(uint32_t s, const void* g) {
    asm volatile("cp.async.cg.shared.global [%0], [%1], 16;" :: "r"(s), "l"(g) : "memory");
}
__device__ __forceinline__ void cp_commit() {
    asm volatile("cp.async.commit_group;" ::: "memory");
}
template <int N> __device__ __forceinline__ void cp_wait() {
    asm volatile("cp.async.wait_group %0;" :: "n"(N) : "memory");
}

__global__ __launch_bounds__(1024, 1)
void fused_conv_kernel(const float* __restrict__ x,
                       const float* __restrict__ w,
                       float* __restrict__ out) {
    const int bx = blockIdx.x;          // 0..111
    const int o  = bx / 56;
    const int kq = (bx / 14) & 3;       // 64-k quarter
    const int h  = bx % 14;
    const int tid = threadIdx.x;
    const int g   = tid >> 6;           // i-group 0..15 (16 i each)
    const int tx  = tid & 63;           // k within quarter
    const int n   = (h + 13) % 14;      // undo roll along H

    const uint32_t s_u32 = (uint32_t)__cvta_generic_to_shared(smem);
    const float* wb = w + (size_t)kq * 192;   // w[i][kq*64 + 0..63][0..2]

    // ---- cp.async weight copy: 2 halves split by il parity ----
    // half c covers il = c*8 .. c*8+7 for every group: rows r 0..127,
    // i = (r>>3)*16 + c*8 + (r&7); 48 f4 per row; 6144 f4 per half.
#define ISSUE_HALF(cc)                                                        \
    {                                                                         \
        _Pragma("unroll")                                                     \
        for (int it = 0; it < 6; it++) {                                      \
            const int f4  = it * 1024 + tid;                                  \
            const int r   = f4 / 48;                                          \
            const int col = f4 % 48;                                          \
            const int i   = (r >> 3) * 16 + (cc) * 8 + (r & 7);               \
            cp16(s_u32 + (uint32_t)(i * 192 + col * 4) * 4,                   \
                 wb + (size_t)i * 768 + col * 4);                             \
        }                                                                     \
        cp_commit();                                                          \
    }
    ISSUE_HALF(0)
    ISSUE_HALF(1)

    // ---- stage x: sxe[i][mm] = xp[mm], sxo[i][mm] = xp[mm+1]
    // xp[a] = (a in [1,14]) ? x[(o*256+i)*196 + n*14 + (a+12)%14] : 0
    {
        const float* xbase = x + ((size_t)o * 256) * 196 + n * 14;
#pragma unroll
        for (int rep = 0; rep < 4; rep++) {
            const int idx = rep * 1024 + tid;      // 0..4095
            const int i = idx >> 4;
            const int mm = idx & 15;
            float ve = 0.f, vo = 0.f;
            if (mm >= 1 && mm <= 14) ve = xbase[(size_t)i * 196 + (mm + 12) % 14];
            if (mm + 1 <= 14)        vo = xbase[(size_t)i * 196 + (mm + 13) % 14];
            smem[SXE_OFF + idx] = ve;
            smem[SXO_OFF + idx] = vo;
        }
    }

    uint64_t A[7];
#pragma unroll
    for (int p = 0; p < 7; p++) A[p] = 0ull;

    // ---- mainloop: two straight-line 8-il runs, 2 barriers total ----
#pragma unroll
    for (int half = 0; half < 2; half++) {
        if (half == 0) cp_wait<1>(); else cp_wait<0>();
        __syncthreads();                 // half's weights (+x staging on half 0) visible

#pragma unroll 4
        for (int q = 0; q < 8; q++) {
            const int il = half * 8 + q;
            const int i  = g * 16 + il;
            const float* swp = smem + (size_t)i * 192 + tx * 3;
            const float* xe  = smem + SXE_OFF + (size_t)i * 16;
            const float* xo  = smem + SXO_OFF + (size_t)i * 16;

            const uint64_t W0 = pk2(swp[0]);
            const uint64_t W1 = pk2(swp[1]);
            const uint64_t W2 = pk2(swp[2]);

            const ulonglong2 e01 = *(const ulonglong2*)(xe);
            const ulonglong2 e23 = *(const ulonglong2*)(xe + 4);
            const ulonglong2 e45 = *(const ulonglong2*)(xe + 8);
            const ulonglong2 e67 = *(const ulonglong2*)(xe + 12);
            const ulonglong2 o01 = *(const ulonglong2*)(xo);
            const ulonglong2 o23 = *(const ulonglong2*)(xo + 4);
            const ulonglong2 o45 = *(const ulonglong2*)(xo + 8);
            const uint64_t   o6  = *(const uint64_t*)  (xo + 12);

            uint64_t E[8] = {e01.x, e01.y, e23.x, e23.y, e45.x, e45.y, e67.x, e67.y};
            uint64_t O[7] = {o01.x, o01.y, o23.x, o23.y, o45.x, o45.y, o6};

#pragma unroll
            for (int p = 0; p < 7; p++) {
                A[p] = ffma2(W0, E[p],     A[p]);
                A[p] = ffma2(W1, O[p],     A[p]);
                A[p] = ffma2(W2, E[p + 1], A[p]);
            }
        }
    }

    // ---- cross-group reduction in smem ----
    __syncthreads();                     // all warps done reading weights
    uint64_t* ps = (uint64_t*)smem;      // ps[g*448 + tx*7 + p], 56KB
#pragma unroll
    for (int p = 0; p < 7; p++)
        ps[(size_t)g * 448 + tx * 7 + p] = A[p];
    __syncthreads();

    if (tid < 448) {
        const int k = tid / 7;           // 0..63
        const int p = tid % 7;
        float vlo = 0.f, vhi = 0.f;
#pragma unroll
        for (int gg = 0; gg < 16; gg++) { // fixed order -> deterministic
            const float2 v = ((const float2*)ps)[gg * 448 + k * 7 + p];
            vlo += v.x;
            vhi += v.y;
        }
        const int cg = o * 256 + kq * 64 + k;
        float2 s; s.x = vlo; s.y = vhi;
        *(float2*)&out[(size_t)cg * 196 + h * 14 + 2 * p] = s;
    }
}

extern "C" void kernel_launch(void* const* d_in, const int* in_sizes, int n_in,
                              void* d_out, int out_size) {
    const float* x = (const float*)d_in[0];   // (1,512,14,14)
    const float* w = (const float*)d_in[1];   // (256,256,3)
    float* out = (float*)d_out;

    cudaFuncSetAttribute(fused_conv_kernel,
                         cudaFuncAttributeMaxDynamicSharedMemorySize, SMEM_BYTES);
    fused_conv_kernel<<<112, 1024, SMEM_BYTES>>>(x, w, out);
}